// round 8
// baseline (speedup 1.0000x reference)
#include <cuda_runtime.h>
#include <math.h>
#include <float.h>

#define T_DIM 512
#define B_DIM 1024
#define V_DIM 96
#define L_DIM 48
#define PKW   50     // packed row: 48 label probs + blank + pad (200 B)

// scratch (no cudaMalloc allowed)
__device__ float  g_pk[(size_t)T_DIM * B_DIM * PKW];   // ~105 MB packed probs
__device__ double g_loss[B_DIM];

// ---------------------------------------------------------------------------
// Kernel G: fused logsumexp + gather + normalize.
// One warp per (t,b) row (row index r = t*B + b).
//   1) 3 coalesced floats/lane -> warp logsumexp over V=96
//   2) lanes 0..23 write exp(x[label(2l)]-lse), exp(x[label(2l+1)]-lse)
//      as float2 to g_pk[r*50 + 2l]; lane 24 writes blank at +48.
// ---------------------------------------------------------------------------
__global__ void __launch_bounds__(256) gather_kernel(const float* __restrict__ y_pred,
                                                     const int*   __restrict__ y_true) {
    int warp = (blockIdx.x * blockDim.x + threadIdx.x) >> 5;  // row id, grid exact
    int lane = threadIdx.x & 31;
    int b = warp & (B_DIM - 1);

    const float* row = y_pred + (size_t)warp * V_DIM;
    float x0 = row[lane];
    float x1 = row[lane + 32];
    float x2 = row[lane + 64];

    float m = fmaxf(x0, fmaxf(x1, x2));
    #pragma unroll
    for (int o = 16; o; o >>= 1) m = fmaxf(m, __shfl_xor_sync(0xFFFFFFFFu, m, o));
    float s = __expf(x0 - m) + __expf(x1 - m) + __expf(x2 - m);
    #pragma unroll
    for (int o = 16; o; o >>= 1) s += __shfl_xor_sync(0xFFFFFFFFu, s, o);
    float lse = m + __logf(s);

    float* out = g_pk + (size_t)warp * PKW;
    if (lane < 24) {
        int2 lp = *(const int2*)(y_true + b * L_DIM + 2 * lane);
        float p0 = __expf(row[lp.x] - lse);   // L1 hits
        float p1 = __expf(row[lp.y] - lse);
        *(float2*)(out + 2 * lane) = make_float2(p0, p1);
    } else if (lane == 24) {
        out[48] = __expf(row[0] - lse);       // blank
    }
}

// ---------------------------------------------------------------------------
// Kernel B: CTC forward recursion on normalized probs from g_pk.
// One WARP per batch element; lane l owns states 4l..4l+3 in registers.
// Per step: one coalesced float2 load, one broadcast load, one __shfl_up.
// FP64 alphas, exact power-of-2 rescale (recenter 2^440) every 16 steps.
// Depth-8 register prefetch queue. Loop covers t=1..504 in PF-blocks plus
// an explicit 7-step tail (t=505..511) -- exactly T-1 = 511 steps, no overrun.
// ---------------------------------------------------------------------------
#define PF 8
__global__ void __launch_bounds__(128) ctc_forward(const int* __restrict__ y_true) {
    const int b = (blockIdx.x * blockDim.x + threadIdx.x) >> 5;   // warp = batch
    const int l = threadIdx.x & 31;

    // skip-transition predicates
    int lab0 = 0, lab1 = 0;
    if (l < 24) {
        int2 lp = *(const int2*)(y_true + b * L_DIM + 2 * l);
        lab0 = lp.x; lab1 = lp.y;
    }
    int prevlab1 = __shfl_up_sync(0xFFFFFFFFu, lab1, 1);
    const double skip1d = (l >= 1 && l < 24 && lab0 != prevlab1) ? 1.0 : 0.0;
    const double skip3d = (l < 24 && lab1 != lab0) ? 1.0 : 0.0;

    const int off2 = (l < 24) ? 2 * l : 0;    // safe addr for inactive lanes
    #define PKBASE(t) (g_pk + ((size_t)(t) * B_DIM + b) * PKW)

    // t = 0: states 0 (blank) and 1 (first label), both on lane 0
    double a0 = 0.0, a1 = 0.0, a2 = 0.0, a3 = 0.0;
    {
        const float* p = PKBASE(0);
        float pb = p[48];
        float p0 = p[0];
        if (l == 0) { a0 = (double)pb; a1 = (double)p0; }
    }

    // prefetch queue for t = 1..PF
    float2 q01[PF];
    float  qb[PF];
    #pragma unroll
    for (int j = 0; j < PF; j++) {
        const float* p = PKBASE(1 + j);
        q01[j] = *(const float2*)(p + off2);
        qb[j]  = p[48];
    }

    int acc_k = 0;   // total power-of-2 shift applied to stored alphas

    // one recursion step (t known at compile time within unrolled bodies)
    #define STEP(t, p01, pb)                                                   \
    {                                                                          \
        double pbd = (double)(pb);                                             \
        double p0d = (double)(p01).x;                                          \
        double p1d = (double)(p01).y;                                          \
        double sh3 = __shfl_up_sync(0xFFFFFFFFu, a3, 1);                       \
        if (l == 0) sh3 = 0.0;                                                 \
        double n0 = (a0 + sh3) * pbd;                                          \
        double n1 = (a0 + a1 + skip1d * sh3) * p0d;                            \
        double n2 = (a1 + a2) * pbd;                                           \
        double n3 = (a2 + a3 + skip3d * a1) * p1d;                             \
        if (l >= 24) { n1 = 0.0; n2 = 0.0; n3 = 0.0; }                         \
        if (l >  24) { n0 = 0.0; }                                             \
        a0 = n0; a1 = n1; a2 = n2; a3 = n3;                                    \
        if (((t) & 15) == 15) {                                                \
            double v = fmax(fmax(a0, a1), fmax(a2, a3));                       \
            _Pragma("unroll")                                                  \
            for (int o = 16; o; o >>= 1)                                       \
                v = fmax(v, __shfl_xor_sync(0xFFFFFFFFu, v, o));               \
            int eb = (__double2hiint(v) >> 20) & 0x7FF;                        \
            int shift = (1023 + 440) - eb;                                     \
            if (shift >  1020) shift =  1020;                                  \
            if (shift < -1020) shift = -1020;                                  \
            double scale = __hiloint2double((1023 + shift) << 20, 0);          \
            a0 *= scale; a1 *= scale; a2 *= scale; a3 *= scale;                \
            acc_k += shift;                                                    \
        }                                                                      \
    }

    // main loop: 63 full blocks of PF steps -> t = 1 .. 504
    for (int tb = 1; tb + PF <= T_DIM; tb += PF) {
        #pragma unroll
        for (int j = 0; j < PF; j++) {
            const int t = tb + j;
            float2 p01 = q01[j];
            float  pb  = qb[j];
            if (t + PF < T_DIM) {                 // refill, consumed PF later
                const float* p = PKBASE(t + PF);
                q01[j] = *(const float2*)(p + off2);
                qb[j]  = p[48];
            }
            STEP(t, p01, pb);
        }
    }
    // tail: t = 505 .. 511 (7 steps, queue slots 0..6, no refill)
    #pragma unroll
    for (int j = 0; j < PF - 1; j++) {
        const int t = (T_DIM - PF + 1) + j;       // 505 + j
        STEP(t, q01[j], qb[j]);
    }
    #undef STEP

    // terminal states: s=95 (lane 23, a3) and s=96 (lane 24, a0)
    double v95 = __shfl_sync(0xFFFFFFFFu, a3, 23);
    double v96 = __shfl_sync(0xFFFFFFFFu, a0, 24);
    if (l == 0) {
        // true_alpha = stored * 2^{-acc_k}; loss = -log(true_alpha)
        g_loss[b] = -log(v95 + v96) + (double)acc_k * 0.6931471805599453094;
    }
    #undef PKBASE
}

// ---------------------------------------------------------------------------
// Kernel C: deterministic mean over B losses -> scalar out
// ---------------------------------------------------------------------------
__global__ void __launch_bounds__(256) mean_kernel(float* __restrict__ out) {
    __shared__ double sh[256];
    int tid = threadIdx.x;
    double s = 0.0;
    #pragma unroll
    for (int i = tid; i < B_DIM; i += 256) s += g_loss[i];
    sh[tid] = s;
    __syncthreads();
    #pragma unroll
    for (int o = 128; o; o >>= 1) {
        if (tid < o) sh[tid] += sh[tid + o];
        __syncthreads();
    }
    if (tid == 0) out[0] = (float)(sh[0] * (1.0 / (double)B_DIM));
}

extern "C" void kernel_launch(void* const* d_in, const int* in_sizes, int n_in,
                              void* d_out, int out_size) {
    const int*   y_true;
    const float* y_pred;
    // pick by size for robustness: y_true has B*L = 49152 elements
    if (in_sizes[0] == B_DIM * L_DIM) {
        y_true = (const int*)d_in[0];
        y_pred = (const float*)d_in[1];
    } else {
        y_true = (const int*)d_in[1];
        y_pred = (const float*)d_in[0];
    }

    // G: fused logsumexp + gather + normalize. 524288 warps, 8 per block.
    gather_kernel<<<(T_DIM * B_DIM) / 8, 256>>>(y_pred, y_true);
    // B: forward recursion, one warp per batch element
    ctc_forward<<<B_DIM / 4, 128>>>(y_true);
    // C: mean
    mean_kernel<<<1, 256>>>((float*)d_out);
}